// round 1
// baseline (speedup 1.0000x reference)
#include <cuda_runtime.h>
#include <math.h>

#define Hh 8
#define Dm 128
#define INSZ 512
#define OUTN 1024
#define HD 1024            // H*D rows
#define SLAB 16384         // D*D
#define SM_SZ 16777216     // H*D*D*D
#define OFF_S 512
#define OFF_SM 131584      // 512 + H*D*D

// scratch: projections (w,z,b,v,k each 1024, then q 128) and per-row scalars
__device__ float g_proj[5 * HD + Dm];
__device__ float g_AL[HD], g_BA[HD], g_U[HD], g_CW[HD], g_CB[HD],
                 g_CV[HD], g_ALP[HD], g_CZ2[HD], g_y[HD];

// ---------------- kernel 1: projections (warp-per-row GEMV) ----------------
__global__ void proj_kernel(const float* __restrict__ x,
                            const float* __restrict__ Ww, const float* __restrict__ Wz,
                            const float* __restrict__ Wb, const float* __restrict__ Wv,
                            const float* __restrict__ Wk, const float* __restrict__ Wq) {
    int warp = (blockIdx.x * blockDim.x + threadIdx.x) >> 5;
    int lane = threadIdx.x & 31;
    if (warp >= 5248) return;
    const float* W;
    int row;
    if (warp < 5120) {
        int t = warp >> 10; row = warp & 1023;
        W = (t == 0) ? Ww : (t == 1) ? Wz : (t == 2) ? Wb : (t == 3) ? Wv : Wk;
    } else { row = warp - 5120; W = Wq; }
    const float* wr = W + (size_t)row * INSZ;
    float s = 0.f;
    for (int m = lane; m < INSZ; m += 32) s += wr[m] * x[m];
    #pragma unroll
    for (int o = 16; o; o >>= 1) s += __shfl_down_sync(0xffffffffu, s, o);
    if (lane == 0) g_proj[warp] = s;
}

// ---------------- kernel 2: per-row scalars + S_new + y partials ----------------
__global__ void row_kernel(const float* __restrict__ S, float* __restrict__ out) {
    int hi = blockIdx.x;          // h*128 + i
    int j  = threadIdx.x;         // 0..127
    int h  = hi >> 7;
    __shared__ float red[4];

    float kj = g_proj[4096 + h * Dm + j];
    float Sj = S[(size_t)hi * Dm + j];

    // sdot = sum_j S[i,j]*k[j]
    float v_ = Sj * kj;
    #pragma unroll
    for (int o = 16; o; o >>= 1) v_ += __shfl_down_sync(0xffffffffu, v_, o);
    if ((j & 31) == 0) red[j >> 5] = v_;
    __syncthreads();
    float sdot = red[0] + red[1] + red[2] + red[3];

    float w  = g_proj[hi];
    float z  = g_proj[1024 + hi];
    float b  = g_proj[2048 + hi];
    float vv = g_proj[3072 + hi];
    float g  = 1.f / (1.f + expf(-w));
    float al = 1.f / (1.f + expf(-z));
    float be = 1.f / (1.f + expf(-b));
    float r_ = al * sdot;
    float u  = be * (g * vv - r_);

    float Snew = al * Sj + u * kj;
    out[OFF_S + (size_t)hi * Dm + j] = Snew;

    // y[h,i] = sum_j S_new[i,j]*q[j]
    float qj = g_proj[5120 + j];
    float yv = Snew * qj;
    #pragma unroll
    for (int o = 16; o; o >>= 1) yv += __shfl_down_sync(0xffffffffu, yv, o);
    __syncthreads();                 // protect red[] reuse
    if ((j & 31) == 0) red[j >> 5] = yv;
    __syncthreads();

    if (j == 0) {
        g_y[hi]  = red[0] + red[1] + red[2] + red[3];
        g_AL[hi] = al;
        g_BA[hi] = be * al;
        g_U[hi]  = u;
        g_CW[hi] = be * g * (1.f - g) * vv;
        g_CB[hi] = be * (1.f - be) * (g * vv - r_);
        g_CV[hi] = be * g;
        float alp = al * (1.f - al);
        g_ALP[hi] = alp;
        g_CZ2[hi] = alp * be * sdot;
    }
}

// ---------------- kernel 3: y @ W_o^T + b_o ----------------
__global__ void out_kernel(const float* __restrict__ Wo, const float* __restrict__ bo,
                           float* __restrict__ out) {
    int warp = (blockIdx.x * blockDim.x + threadIdx.x) >> 5;
    int lane = threadIdx.x & 31;
    if (warp >= INSZ) return;
    const float* wr = Wo + (size_t)warp * OUTN;
    float s = 0.f;
    for (int m = lane; m < OUTN; m += 32) s += wr[m] * g_y[m];
    #pragma unroll
    for (int o = 16; o; o >>= 1) s += __shfl_down_sync(0xffffffffu, s, o);
    if (lane == 0) out[warp] = s + bo[warp];
}

// ---------------- kernel 4: the 670MB sensitivity update ----------------
// One block per (tensor t, h, i) slab P[j,c] of 128x128.
// Thread (part, c): caches 16 P[j,c] in registers, builds contr[c] via smem,
// writes update. Each element: exactly 1 global read + 1 global write.
__global__ void __launch_bounds__(1024, 1) slab_kernel(
    const float* __restrict__ P0, const float* __restrict__ P1,
    const float* __restrict__ P2, const float* __restrict__ P3,
    const float* __restrict__ P4, const float* __restrict__ S,
    float* __restrict__ out) {
    int bx = blockIdx.x;
    int t  = bx >> 10;
    int hi = bx & 1023;
    int h  = hi >> 7;
    int i  = hi & 127;
    int tid  = threadIdx.x;
    int c    = tid & 127;
    int part = tid >> 7;      // 0..7
    int j0   = part * 16;

    __shared__ float k_s[128], S_s[128], part_s[8][128];
    if (tid < 128) {
        k_s[tid] = g_proj[4096 + h * 128 + tid];
        S_s[tid] = S[(size_t)hi * 128 + tid];
    }
    __syncthreads();

    const float* P = ((t == 0) ? P0 : (t == 1) ? P1 : (t == 2) ? P2 :
                      (t == 3) ? P3 : P4) + (size_t)hi * SLAB;

    float p[16];
    float cp = 0.f;
    #pragma unroll
    for (int jj = 0; jj < 16; jj++) {
        int j = j0 + jj;
        p[jj] = P[j * 128 + c];
        cp += k_s[j] * p[jj];
    }
    part_s[part][c] = cp;
    __syncthreads();
    float contr = 0.f;
    #pragma unroll
    for (int pp = 0; pp < 8; pp++) contr += part_s[pp][c];

    float al = g_AL[hi];
    float ba = g_BA[hi];
    float* op = out + OFF_SM + (size_t)t * SM_SZ + (size_t)hi * SLAB;

    if (t == 4) {
        // D_k[i,j,c] = u_i * delta_{jc} - ba_i * S[i,c] * k_j
        float u  = g_U[hi];
        float sc = ba * S_s[c];
        #pragma unroll
        for (int jj = 0; jj < 16; jj++) {
            int j = j0 + jj;
            float val = al * p[jj] - (ba * contr + sc) * k_s[j];
            if (j == c) val += u;
            op[j * 128 + c] = val;
        }
    } else {
        // direct terms live only in column c == i
        float cfK = 0.f, cfS = 0.f;
        if (t == 0)       cfK = g_CW[hi];
        else if (t == 1) { cfK = -g_CZ2[hi]; cfS = g_ALP[hi]; }
        else if (t == 2)  cfK = g_CB[hi];
        else              cfK = g_CV[hi];
        bool diag = (c == i);
        #pragma unroll
        for (int jj = 0; jj < 16; jj++) {
            int j = j0 + jj;
            float val = al * p[jj] - ba * k_s[j] * contr;
            if (diag) val += cfK * k_s[j] + cfS * S_s[j];
            op[j * 128 + c] = val;
        }
    }
}

extern "C" void kernel_launch(void* const* d_in, const int* in_sizes, int n_in,
                              void* d_out, int out_size) {
    const float* x    = (const float*)d_in[0];
    const float* S    = (const float*)d_in[1];
    const float* sm_w = (const float*)d_in[2];
    const float* sm_z = (const float*)d_in[3];
    const float* sm_b = (const float*)d_in[4];
    const float* sm_v = (const float*)d_in[5];
    const float* sm_k = (const float*)d_in[6];
    const float* W_w  = (const float*)d_in[7];
    const float* W_z  = (const float*)d_in[8];
    const float* W_b  = (const float*)d_in[9];
    const float* W_v  = (const float*)d_in[10];
    const float* W_k  = (const float*)d_in[11];
    const float* W_q  = (const float*)d_in[12];
    const float* W_o  = (const float*)d_in[13];
    const float* b_o  = (const float*)d_in[14];
    float* out = (float*)d_out;

    proj_kernel<<<656, 256>>>(x, W_w, W_z, W_b, W_v, W_k, W_q);
    row_kernel<<<1024, 128>>>(S, out);
    out_kernel<<<64, 256>>>(W_o, b_o, out);
    slab_kernel<<<5120, 1024>>>(sm_w, sm_z, sm_b, sm_v, sm_k, S, out);
}

// round 4
// speedup vs baseline: 1.4480x; 1.4480x over previous
#include <cuda_runtime.h>
#include <math.h>

#define Hh 8
#define Dm 128
#define INSZ 512
#define OUTN 1024
#define HD 1024            // H*D rows
#define SLAB 16384         // D*D
#define SM_SZ 16777216     // H*D*D*D
#define OFF_S 512
#define OFF_SM 131584      // 512 + H*D*D

// scratch: projections (w,z,b,v,k each 1024, then q 128) and per-row scalars
__device__ float g_proj[5 * HD + Dm];
__device__ float g_AL[HD], g_BA[HD], g_U[HD], g_CW[HD], g_CB[HD],
                 g_CV[HD], g_ALP[HD], g_CZ2[HD], g_y[HD];

// ---------------- kernel 1: projections (warp-per-row GEMV) ----------------
__global__ void proj_kernel(const float* __restrict__ x,
                            const float* __restrict__ Ww, const float* __restrict__ Wz,
                            const float* __restrict__ Wb, const float* __restrict__ Wv,
                            const float* __restrict__ Wk, const float* __restrict__ Wq) {
    int warp = (blockIdx.x * blockDim.x + threadIdx.x) >> 5;
    int lane = threadIdx.x & 31;
    if (warp >= 5248) return;
    const float* W;
    int row;
    if (warp < 5120) {
        int t = warp >> 10; row = warp & 1023;
        W = (t == 0) ? Ww : (t == 1) ? Wz : (t == 2) ? Wb : (t == 3) ? Wv : Wk;
    } else { row = warp - 5120; W = Wq; }
    const float* wr = W + (size_t)row * INSZ;
    float s = 0.f;
    for (int m = lane; m < INSZ; m += 32) s += wr[m] * x[m];
    #pragma unroll
    for (int o = 16; o; o >>= 1) s += __shfl_down_sync(0xffffffffu, s, o);
    if (lane == 0) g_proj[warp] = s;
}

// ---------------- kernel 2: per-row scalars + S_new + y partials ----------------
__global__ void row_kernel(const float* __restrict__ S, float* __restrict__ out) {
    int hi = blockIdx.x;          // h*128 + i
    int j  = threadIdx.x;         // 0..127
    int h  = hi >> 7;
    __shared__ float red[4];

    float kj = g_proj[4096 + h * Dm + j];
    float Sj = S[(size_t)hi * Dm + j];

    // sdot = sum_j S[i,j]*k[j]
    float v_ = Sj * kj;
    #pragma unroll
    for (int o = 16; o; o >>= 1) v_ += __shfl_down_sync(0xffffffffu, v_, o);
    if ((j & 31) == 0) red[j >> 5] = v_;
    __syncthreads();
    float sdot = red[0] + red[1] + red[2] + red[3];

    float w  = g_proj[hi];
    float z  = g_proj[1024 + hi];
    float b  = g_proj[2048 + hi];
    float vv = g_proj[3072 + hi];
    float g  = 1.f / (1.f + expf(-w));
    float al = 1.f / (1.f + expf(-z));
    float be = 1.f / (1.f + expf(-b));
    float r_ = al * sdot;
    float u  = be * (g * vv - r_);

    float Snew = al * Sj + u * kj;
    out[OFF_S + (size_t)hi * Dm + j] = Snew;

    // y[h,i] = sum_j S_new[i,j]*q[j]
    float qj = g_proj[5120 + j];
    float yv = Snew * qj;
    #pragma unroll
    for (int o = 16; o; o >>= 1) yv += __shfl_down_sync(0xffffffffu, yv, o);
    __syncthreads();                 // protect red[] reuse
    if ((j & 31) == 0) red[j >> 5] = yv;
    __syncthreads();

    if (j == 0) {
        g_y[hi]  = red[0] + red[1] + red[2] + red[3];
        g_AL[hi] = al;
        g_BA[hi] = be * al;
        g_U[hi]  = u;
        g_CW[hi] = be * g * (1.f - g) * vv;
        g_CB[hi] = be * (1.f - be) * (g * vv - r_);
        g_CV[hi] = be * g;
        float alp = al * (1.f - al);
        g_ALP[hi] = alp;
        g_CZ2[hi] = alp * be * sdot;
    }
}

// ---------------- kernel 3: the 670MB sensitivity update (v2) ----------------
// Two blocks per (t,h,i) slab; each block handles 64 columns (a half-slab).
// 256 threads = (part 0..15, cq 0..15): thread owns 8 j-rows x 4 contiguous
// columns, cached in registers as float4. 1 LDG.128 + 1 STG.128 per row.
// First 512 blocks also compute one row of y @ W_o^T + b_o (folded out_kernel).
__global__ void __launch_bounds__(256, 4) slab_kernel(
    const float* __restrict__ P0, const float* __restrict__ P1,
    const float* __restrict__ P2, const float* __restrict__ P3,
    const float* __restrict__ P4, const float* __restrict__ S,
    const float* __restrict__ Wo, const float* __restrict__ bo,
    float* __restrict__ out) {
    int bx  = blockIdx.x;         // 0..10239
    int tid = threadIdx.x;

    // folded output projection: out[row] = Wo[row,:] . y + bo[row]
    if (bx < INSZ && tid < 32) {
        const float* wr = Wo + (size_t)bx * OUTN;
        float s = 0.f;
        for (int m = tid; m < OUTN; m += 32) s += wr[m] * g_y[m];
        #pragma unroll
        for (int o = 16; o; o >>= 1) s += __shfl_down_sync(0xffffffffu, s, o);
        if (tid == 0) out[bx] = s + bo[bx];
    }

    int half = bx & 1;
    int sb   = bx >> 1;           // slab id 0..5119
    int t    = sb >> 10;
    int hi   = sb & 1023;
    int h    = hi >> 7;
    int i    = hi & 127;
    int cq   = tid & 15;
    int part = tid >> 4;          // 0..15, owns j in [part*8, part*8+8)
    int c0   = half * 64 + cq * 4;

    __shared__ float k_s[128], S_s[128];
    __shared__ float4 red4[16][16];
    if (tid < 128) {
        k_s[tid] = g_proj[4096 + h * 128 + tid];
        S_s[tid] = S[(size_t)hi * 128 + tid];
    }
    __syncthreads();

    const float* P = ((t == 0) ? P0 : (t == 1) ? P1 : (t == 2) ? P2 :
                      (t == 3) ? P3 : P4) + (size_t)hi * SLAB;

    float4 p[8];
    float4 cp = make_float4(0.f, 0.f, 0.f, 0.f);
    #pragma unroll
    for (int jj = 0; jj < 8; jj++) {
        int j = part * 8 + jj;
        p[jj] = __ldcs((const float4*)(P + j * 128 + c0));
        float kj = k_s[j];
        cp.x += kj * p[jj].x;
        cp.y += kj * p[jj].y;
        cp.z += kj * p[jj].z;
        cp.w += kj * p[jj].w;
    }
    red4[part][cq] = cp;
    __syncthreads();

    float4 contr = make_float4(0.f, 0.f, 0.f, 0.f);
    #pragma unroll
    for (int pp = 0; pp < 16; pp++) {
        float4 r = red4[pp][cq];
        contr.x += r.x; contr.y += r.y; contr.z += r.z; contr.w += r.w;
    }

    float al = g_AL[hi];
    float ba = g_BA[hi];
    float* op = out + OFF_SM + (size_t)t * SM_SZ + (size_t)hi * SLAB;

    if (t == 4) {
        // D_k[i,j,c] = u_i*delta_{jc} - ba_i*S[i,c]*k_j ; rec term shared
        float u = g_U[hi];
        float Ax = ba * contr.x + ba * S_s[c0 + 0];
        float Ay = ba * contr.y + ba * S_s[c0 + 1];
        float Az = ba * contr.z + ba * S_s[c0 + 2];
        float Aw = ba * contr.w + ba * S_s[c0 + 3];
        #pragma unroll
        for (int jj = 0; jj < 8; jj++) {
            int j = part * 8 + jj;
            float kj = k_s[j];
            float4 v;
            v.x = al * p[jj].x - Ax * kj;
            v.y = al * p[jj].y - Ay * kj;
            v.z = al * p[jj].z - Az * kj;
            v.w = al * p[jj].w - Aw * kj;
            if (j == c0 + 0) v.x += u;
            if (j == c0 + 1) v.y += u;
            if (j == c0 + 2) v.z += u;
            if (j == c0 + 3) v.w += u;
            __stcs((float4*)(op + j * 128 + c0), v);
        }
    } else {
        // direct terms live only in column c == i
        float cfK, cfS = 0.f;
        if (t == 0)       cfK = g_CW[hi];
        else if (t == 1) { cfK = -g_CZ2[hi]; cfS = g_ALP[hi]; }
        else if (t == 2)  cfK = g_CB[hi];
        else              cfK = g_CV[hi];
        float fx = (c0 + 0 == i) ? 1.f : 0.f;
        float fy = (c0 + 1 == i) ? 1.f : 0.f;
        float fz = (c0 + 2 == i) ? 1.f : 0.f;
        float fw = (c0 + 3 == i) ? 1.f : 0.f;
        float bcx = ba * contr.x, bcy = ba * contr.y;
        float bcz = ba * contr.z, bcw = ba * contr.w;
        #pragma unroll
        for (int jj = 0; jj < 8; jj++) {
            int j = part * 8 + jj;
            float kj = k_s[j];
            float dterm = cfK * kj + cfS * S_s[j];
            float4 v;
            v.x = al * p[jj].x - bcx * kj + fx * dterm;
            v.y = al * p[jj].y - bcy * kj + fy * dterm;
            v.z = al * p[jj].z - bcz * kj + fz * dterm;
            v.w = al * p[jj].w - bcw * kj + fw * dterm;
            __stcs((float4*)(op + j * 128 + c0), v);
        }
    }
}

extern "C" void kernel_launch(void* const* d_in, const int* in_sizes, int n_in,
                              void* d_out, int out_size) {
    const float* x    = (const float*)d_in[0];
    const float* S    = (const float*)d_in[1];
    const float* sm_w = (const float*)d_in[2];
    const float* sm_z = (const float*)d_in[3];
    const float* sm_b = (const float*)d_in[4];
    const float* sm_v = (const float*)d_in[5];
    const float* sm_k = (const float*)d_in[6];
    const float* W_w  = (const float*)d_in[7];
    const float* W_z  = (const float*)d_in[8];
    const float* W_b  = (const float*)d_in[9];
    const float* W_v  = (const float*)d_in[10];
    const float* W_k  = (const float*)d_in[11];
    const float* W_q  = (const float*)d_in[12];
    const float* W_o  = (const float*)d_in[13];
    const float* b_o  = (const float*)d_in[14];
    float* out = (float*)d_out;

    proj_kernel<<<656, 256>>>(x, W_w, W_z, W_b, W_v, W_k, W_q);
    row_kernel<<<1024, 128>>>(S, out);
    slab_kernel<<<10240, 256>>>(sm_w, sm_z, sm_b, sm_v, sm_k, S, W_o, b_o, out);
}

// round 6
// speedup vs baseline: 1.4505x; 1.0017x over previous
#include <cuda_runtime.h>
#include <math.h>

#define Hh 8
#define Dm 128
#define INSZ 512
#define OUTN 1024
#define HD 1024            // H*D rows
#define SLAB 16384         // D*D
#define SM_SZ 16777216     // H*D*D*D
#define OFF_S 512
#define OFF_SM 131584      // 512 + H*D*D

// scratch: k/q projections and per-row scalars
__device__ float g_k[HD], g_q[Dm];
__device__ float g_AL[HD], g_BA[HD], g_U[HD], g_CW[HD], g_CB[HD],
                 g_CV[HD], g_ALP[HD], g_CZ2[HD], g_y[HD];

// ---------------- kernel 1: k,q projections (warp-per-row GEMV, float4) ----
__global__ void proj_kernel(const float* __restrict__ x,
                            const float* __restrict__ Wk,
                            const float* __restrict__ Wq) {
    int warp = (blockIdx.x * blockDim.x + threadIdx.x) >> 5;
    int lane = threadIdx.x & 31;
    if (warp >= HD + Dm) return;
    const float* wr = (warp < HD) ? (Wk + (size_t)warp * INSZ)
                                  : (Wq + (size_t)(warp - HD) * INSZ);
    const float4* w4 = (const float4*)wr;
    const float4* x4 = (const float4*)x;
    float s = 0.f;
    #pragma unroll
    for (int m = lane; m < INSZ / 4; m += 32) {
        float4 a = w4[m], b = x4[m];
        s += a.x * b.x + a.y * b.y + a.z * b.z + a.w * b.w;
    }
    #pragma unroll
    for (int o = 16; o; o >>= 1) s += __shfl_down_sync(0xffffffffu, s, o);
    if (lane == 0) {
        if (warp < HD) g_k[warp] = s;
        else           g_q[warp - HD] = s;
    }
}

// ---------------- kernel 2: per-row proj(w,z,b,v) + scalars + S_new + y ----
__global__ void row_kernel(const float* __restrict__ x, const float* __restrict__ S,
                           const float* __restrict__ Ww, const float* __restrict__ Wz,
                           const float* __restrict__ Wb, const float* __restrict__ Wv,
                           float* __restrict__ out) {
    int hi = blockIdx.x;          // h*128 + i
    int j  = threadIdx.x;         // 0..127
    int h  = hi >> 7;
    int wq = j >> 5, lane = j & 31;
    __shared__ float red[5][4];
    __shared__ float sc[2];

    // inline projections: thread j owns input slice m = 4j..4j+3
    float4 xv = ((const float4*)x)[j];
    size_t ro = (size_t)hi * (INSZ / 4);
    float4 aw = ((const float4*)Ww)[ro + j];
    float4 az = ((const float4*)Wz)[ro + j];
    float4 ab = ((const float4*)Wb)[ro + j];
    float4 av = ((const float4*)Wv)[ro + j];
    float pw = aw.x * xv.x + aw.y * xv.y + aw.z * xv.z + aw.w * xv.w;
    float pz = az.x * xv.x + az.y * xv.y + az.z * xv.z + az.w * xv.w;
    float pb = ab.x * xv.x + ab.y * xv.y + ab.z * xv.z + ab.w * xv.w;
    float pv = av.x * xv.x + av.y * xv.y + av.z * xv.z + av.w * xv.w;

    float kj = g_k[h * Dm + j];
    float Sj = S[(size_t)hi * Dm + j];
    float ps = Sj * kj;           // sdot partial

    #pragma unroll
    for (int o = 16; o; o >>= 1) {
        pw += __shfl_down_sync(0xffffffffu, pw, o);
        pz += __shfl_down_sync(0xffffffffu, pz, o);
        pb += __shfl_down_sync(0xffffffffu, pb, o);
        pv += __shfl_down_sync(0xffffffffu, pv, o);
        ps += __shfl_down_sync(0xffffffffu, ps, o);
    }
    if (lane == 0) {
        red[0][wq] = pw; red[1][wq] = pz; red[2][wq] = pb;
        red[3][wq] = pv; red[4][wq] = ps;
    }
    __syncthreads();

    if (j == 0) {
        float w  = red[0][0] + red[0][1] + red[0][2] + red[0][3];
        float z  = red[1][0] + red[1][1] + red[1][2] + red[1][3];
        float b  = red[2][0] + red[2][1] + red[2][2] + red[2][3];
        float vv = red[3][0] + red[3][1] + red[3][2] + red[3][3];
        float sdot = red[4][0] + red[4][1] + red[4][2] + red[4][3];
        float g  = 1.f / (1.f + expf(-w));
        float al = 1.f / (1.f + expf(-z));
        float be = 1.f / (1.f + expf(-b));
        float r_ = al * sdot;
        float u  = be * (g * vv - r_);
        g_AL[hi] = al;
        g_BA[hi] = be * al;
        g_U[hi]  = u;
        g_CW[hi] = be * g * (1.f - g) * vv;
        g_CB[hi] = be * (1.f - be) * (g * vv - r_);
        g_CV[hi] = be * g;
        float alp = al * (1.f - al);
        g_ALP[hi] = alp;
        g_CZ2[hi] = alp * be * sdot;
        sc[0] = al; sc[1] = u;
    }
    __syncthreads();

    float al = sc[0], u = sc[1];
    float Snew = al * Sj + u * kj;
    out[OFF_S + (size_t)hi * Dm + j] = Snew;

    // y[hi] = sum_j Snew * q[j]
    float yv = Snew * g_q[j];
    #pragma unroll
    for (int o = 16; o; o >>= 1) yv += __shfl_down_sync(0xffffffffu, yv, o);
    __syncthreads();
    if (lane == 0) red[0][wq] = yv;
    __syncthreads();
    if (j == 0) g_y[hi] = red[0][0] + red[0][1] + red[0][2] + red[0][3];
}

// ---------------- kernel 3: the 670MB sensitivity update ----------------
// Two blocks per (t,h,i) slab; each block handles 64 columns.
// 256 threads = (part 0..15, cq 0..15): thread owns 8 j-rows x 4 contiguous
// columns in registers as float4. 1 LDG.128 + 1 STG.128 per row.
// First 512 blocks also compute one row of y @ W_o^T + b_o.
__global__ void __launch_bounds__(256, 5) slab_kernel(
    const float* __restrict__ P0, const float* __restrict__ P1,
    const float* __restrict__ P2, const float* __restrict__ P3,
    const float* __restrict__ P4, const float* __restrict__ S,
    const float* __restrict__ Wo, const float* __restrict__ bo,
    float* __restrict__ out) {
    int bx  = blockIdx.x;         // 0..10239
    int tid = threadIdx.x;

    // folded output projection: out[row] = Wo[row,:] . y + bo[row]
    if (bx < INSZ && tid < 32) {
        const float4* wr = (const float4*)(Wo + (size_t)bx * OUTN);
        float s = 0.f;
        for (int m = tid; m < OUTN / 4; m += 32) {
            float4 a = wr[m];
            s += a.x * g_y[m * 4] + a.y * g_y[m * 4 + 1]
               + a.z * g_y[m * 4 + 2] + a.w * g_y[m * 4 + 3];
        }
        #pragma unroll
        for (int o = 16; o; o >>= 1) s += __shfl_down_sync(0xffffffffu, s, o);
        if (tid == 0) out[bx] = s + bo[bx];
    }

    int half = bx & 1;
    int sb   = bx >> 1;           // slab id 0..5119
    int t    = sb >> 10;
    int hi   = sb & 1023;
    int h    = hi >> 7;
    int i    = hi & 127;
    int cq   = tid & 15;
    int part = tid >> 4;          // 0..15, owns j in [part*8, part*8+8)
    int c0   = half * 64 + cq * 4;

    __shared__ float k_s[128], S_s[128];
    __shared__ float4 red4[16][16];
    if (tid < 128) {
        k_s[tid] = g_k[h * 128 + tid];
        S_s[tid] = S[(size_t)hi * 128 + tid];
    }
    __syncthreads();

    const float* P = ((t == 0) ? P0 : (t == 1) ? P1 : (t == 2) ? P2 :
                      (t == 3) ? P3 : P4) + (size_t)hi * SLAB;

    float4 p[8];
    float4 cp = make_float4(0.f, 0.f, 0.f, 0.f);
    #pragma unroll
    for (int jj = 0; jj < 8; jj++) {
        int j = part * 8 + jj;
        p[jj] = __ldcs((const float4*)(P + j * 128 + c0));
        float kj = k_s[j];
        cp.x += kj * p[jj].x;
        cp.y += kj * p[jj].y;
        cp.z += kj * p[jj].z;
        cp.w += kj * p[jj].w;
    }
    red4[part][cq] = cp;
    __syncthreads();

    float4 contr = make_float4(0.f, 0.f, 0.f, 0.f);
    #pragma unroll
    for (int pp = 0; pp < 16; pp++) {
        float4 r = red4[pp][cq];
        contr.x += r.x; contr.y += r.y; contr.z += r.z; contr.w += r.w;
    }

    float al = g_AL[hi];
    float ba = g_BA[hi];
    float* op = out + OFF_SM + (size_t)t * SM_SZ + (size_t)hi * SLAB;

    if (t == 4) {
        // D_k[i,j,c] = u_i*delta_{jc} - ba_i*S[i,c]*k_j ; rec term shared
        float u = g_U[hi];
        float Ax = ba * contr.x + ba * S_s[c0 + 0];
        float Ay = ba * contr.y + ba * S_s[c0 + 1];
        float Az = ba * contr.z + ba * S_s[c0 + 2];
        float Aw = ba * contr.w + ba * S_s[c0 + 3];
        #pragma unroll
        for (int jj = 0; jj < 8; jj++) {
            int j = part * 8 + jj;
            float kj = k_s[j];
            float4 v;
            v.x = al * p[jj].x - Ax * kj;
            v.y = al * p[jj].y - Ay * kj;
            v.z = al * p[jj].z - Az * kj;
            v.w = al * p[jj].w - Aw * kj;
            if (j == c0 + 0) v.x += u;
            if (j == c0 + 1) v.y += u;
            if (j == c0 + 2) v.z += u;
            if (j == c0 + 3) v.w += u;
            __stcs((float4*)(op + j * 128 + c0), v);
        }
    } else {
        // direct terms live only in column c == i
        float cfK, cfS = 0.f;
        if (t == 0)       cfK = g_CW[hi];
        else if (t == 1) { cfK = -g_CZ2[hi]; cfS = g_ALP[hi]; }
        else if (t == 2)  cfK = g_CB[hi];
        else              cfK = g_CV[hi];
        float fx = (c0 + 0 == i) ? 1.f : 0.f;
        float fy = (c0 + 1 == i) ? 1.f : 0.f;
        float fz = (c0 + 2 == i) ? 1.f : 0.f;
        float fw = (c0 + 3 == i) ? 1.f : 0.f;
        float bcx = ba * contr.x, bcy = ba * contr.y;
        float bcz = ba * contr.z, bcw = ba * contr.w;
        #pragma unroll
        for (int jj = 0; jj < 8; jj++) {
            int j = part * 8 + jj;
            float kj = k_s[j];
            float dterm = cfK * kj + cfS * S_s[j];
            float4 v;
            v.x = al * p[jj].x - bcx * kj + fx * dterm;
            v.y = al * p[jj].y - bcy * kj + fy * dterm;
            v.z = al * p[jj].z - bcz * kj + fz * dterm;
            v.w = al * p[jj].w - bcw * kj + fw * dterm;
            __stcs((float4*)(op + j * 128 + c0), v);
        }
    }
}

extern "C" void kernel_launch(void* const* d_in, const int* in_sizes, int n_in,
                              void* d_out, int out_size) {
    const float* x    = (const float*)d_in[0];
    const float* S    = (const float*)d_in[1];
    const float* sm_w = (const float*)d_in[2];
    const float* sm_z = (const float*)d_in[3];
    const float* sm_b = (const float*)d_in[4];
    const float* sm_v = (const float*)d_in[5];
    const float* sm_k = (const float*)d_in[6];
    const float* W_w  = (const float*)d_in[7];
    const float* W_z  = (const float*)d_in[8];
    const float* W_b  = (const float*)d_in[9];
    const float* W_v  = (const float*)d_in[10];
    const float* W_k  = (const float*)d_in[11];
    const float* W_q  = (const float*)d_in[12];
    const float* W_o  = (const float*)d_in[13];
    const float* b_o  = (const float*)d_in[14];
    float* out = (float*)d_out;

    proj_kernel<<<144, 256>>>(x, W_k, W_q);
    row_kernel<<<1024, 128>>>(x, S, W_w, W_z, W_b, W_v, out);
    slab_kernel<<<10240, 256>>>(sm_w, sm_z, sm_b, sm_v, sm_k, S, W_o, b_o, out);
}

// round 7
// speedup vs baseline: 1.5117x; 1.0422x over previous
#include <cuda_runtime.h>
#include <math.h>

#define Hh 8
#define Dm 128
#define INSZ 512
#define OUTN 1024
#define HD 1024            // H*D rows
#define SLAB 16384         // D*D
#define SM_SZ 16777216     // H*D*D*D
#define OFF_S 512
#define OFF_SM 131584      // 512 + H*D*D

// scratch: k/q projections and per-row scalars
__device__ float g_k[HD], g_q[Dm];
__device__ float g_AL[HD], g_BA[HD], g_U[HD], g_CW[HD], g_CB[HD],
                 g_CV[HD], g_ALP[HD], g_CZ2[HD], g_y[HD];

// ---------------- kernel 1: k,q projections (warp-per-row GEMV, float4) ----
__global__ void proj_kernel(const float* __restrict__ x,
                            const float* __restrict__ Wk,
                            const float* __restrict__ Wq) {
    int warp = (blockIdx.x * blockDim.x + threadIdx.x) >> 5;
    int lane = threadIdx.x & 31;
    if (warp >= HD + Dm) return;
    const float* wr = (warp < HD) ? (Wk + (size_t)warp * INSZ)
                                  : (Wq + (size_t)(warp - HD) * INSZ);
    const float4* w4 = (const float4*)wr;
    const float4* x4 = (const float4*)x;
    float s = 0.f;
    #pragma unroll
    for (int m = lane; m < INSZ / 4; m += 32) {
        float4 a = w4[m], b = x4[m];
        s += a.x * b.x + a.y * b.y + a.z * b.z + a.w * b.w;
    }
    #pragma unroll
    for (int o = 16; o; o >>= 1) s += __shfl_down_sync(0xffffffffu, s, o);
    if (lane == 0) {
        if (warp < HD) g_k[warp] = s;
        else           g_q[warp - HD] = s;
    }
}

// ---------------- kernel 2: per-row proj(w,z,b,v) + scalars + S_new + y ----
__global__ void row_kernel(const float* __restrict__ x, const float* __restrict__ S,
                           const float* __restrict__ Ww, const float* __restrict__ Wz,
                           const float* __restrict__ Wb, const float* __restrict__ Wv,
                           float* __restrict__ out) {
    int hi = blockIdx.x;          // h*128 + i
    int j  = threadIdx.x;         // 0..127
    int h  = hi >> 7;
    int wq = j >> 5, lane = j & 31;
    __shared__ float red[5][4];
    __shared__ float sc[2];

    // inline projections: thread j owns input slice m = 4j..4j+3
    float4 xv = ((const float4*)x)[j];
    size_t ro = (size_t)hi * (INSZ / 4);
    float4 aw = ((const float4*)Ww)[ro + j];
    float4 az = ((const float4*)Wz)[ro + j];
    float4 ab = ((const float4*)Wb)[ro + j];
    float4 av = ((const float4*)Wv)[ro + j];
    float pw = aw.x * xv.x + aw.y * xv.y + aw.z * xv.z + aw.w * xv.w;
    float pz = az.x * xv.x + az.y * xv.y + az.z * xv.z + az.w * xv.w;
    float pb = ab.x * xv.x + ab.y * xv.y + ab.z * xv.z + ab.w * xv.w;
    float pv = av.x * xv.x + av.y * xv.y + av.z * xv.z + av.w * xv.w;

    float kj = g_k[h * Dm + j];
    float Sj = S[(size_t)hi * Dm + j];
    float ps = Sj * kj;           // sdot partial

    #pragma unroll
    for (int o = 16; o; o >>= 1) {
        pw += __shfl_down_sync(0xffffffffu, pw, o);
        pz += __shfl_down_sync(0xffffffffu, pz, o);
        pb += __shfl_down_sync(0xffffffffu, pb, o);
        pv += __shfl_down_sync(0xffffffffu, pv, o);
        ps += __shfl_down_sync(0xffffffffu, ps, o);
    }
    if (lane == 0) {
        red[0][wq] = pw; red[1][wq] = pz; red[2][wq] = pb;
        red[3][wq] = pv; red[4][wq] = ps;
    }
    __syncthreads();

    if (j == 0) {
        float w  = red[0][0] + red[0][1] + red[0][2] + red[0][3];
        float z  = red[1][0] + red[1][1] + red[1][2] + red[1][3];
        float b  = red[2][0] + red[2][1] + red[2][2] + red[2][3];
        float vv = red[3][0] + red[3][1] + red[3][2] + red[3][3];
        float sdot = red[4][0] + red[4][1] + red[4][2] + red[4][3];
        float g  = 1.f / (1.f + expf(-w));
        float al = 1.f / (1.f + expf(-z));
        float be = 1.f / (1.f + expf(-b));
        float r_ = al * sdot;
        float u  = be * (g * vv - r_);
        g_AL[hi] = al;
        g_BA[hi] = be * al;
        g_U[hi]  = u;
        g_CW[hi] = be * g * (1.f - g) * vv;
        g_CB[hi] = be * (1.f - be) * (g * vv - r_);
        g_CV[hi] = be * g;
        float alp = al * (1.f - al);
        g_ALP[hi] = alp;
        g_CZ2[hi] = alp * be * sdot;
        sc[0] = al; sc[1] = u;
    }
    __syncthreads();

    float al = sc[0], u = sc[1];
    float Snew = al * Sj + u * kj;
    out[OFF_S + (size_t)hi * Dm + j] = Snew;

    // y[hi] = sum_j Snew * q[j]
    float yv = Snew * g_q[j];
    #pragma unroll
    for (int o = 16; o; o >>= 1) yv += __shfl_down_sync(0xffffffffu, yv, o);
    __syncthreads();
    if (lane == 0) red[0][wq] = yv;
    __syncthreads();
    if (j == 0) g_y[hi] = red[0][0] + red[0][1] + red[0][2] + red[0][3];
}

// ---------------- kernel 3: the 670MB sensitivity update ----------------
// Two blocks per (t,h,i) slab; each block handles 64 columns.
// 256 threads = (part 0..15, cq 0..15): thread owns 8 j-rows x 4 contiguous
// columns in registers as float4. 1 LDG.128 + 1 STG.128 per row.
// First 512 blocks also compute one row of y @ W_o^T + b_o.
__global__ void __launch_bounds__(256, 4) slab_kernel(
    const float* __restrict__ P0, const float* __restrict__ P1,
    const float* __restrict__ P2, const float* __restrict__ P3,
    const float* __restrict__ P4, const float* __restrict__ S,
    const float* __restrict__ Wo, const float* __restrict__ bo,
    float* __restrict__ out) {
    int bx  = blockIdx.x;         // 0..10239
    int tid = threadIdx.x;

    // folded output projection: out[row] = Wo[row,:] . y + bo[row]
    if (bx < INSZ && tid < 32) {
        const float4* wr = (const float4*)(Wo + (size_t)bx * OUTN);
        float s = 0.f;
        for (int m = tid; m < OUTN / 4; m += 32) {
            float4 a = wr[m];
            s += a.x * g_y[m * 4] + a.y * g_y[m * 4 + 1]
               + a.z * g_y[m * 4 + 2] + a.w * g_y[m * 4 + 3];
        }
        #pragma unroll
        for (int o = 16; o; o >>= 1) s += __shfl_down_sync(0xffffffffu, s, o);
        if (tid == 0) out[bx] = s + bo[bx];
    }

    int half = bx & 1;
    int sb   = bx >> 1;           // slab id 0..5119
    int t    = sb >> 10;
    int hi   = sb & 1023;
    int h    = hi >> 7;
    int i    = hi & 127;
    int cq   = tid & 15;
    int part = tid >> 4;          // 0..15, owns j in [part*8, part*8+8)
    int c0   = half * 64 + cq * 4;

    __shared__ float k_s[128], S_s[128];
    __shared__ float4 red4[16][16];
    if (tid < 128) {
        k_s[tid] = g_k[h * 128 + tid];
        S_s[tid] = S[(size_t)hi * 128 + tid];
    }
    __syncthreads();

    const float* P = ((t == 0) ? P0 : (t == 1) ? P1 : (t == 2) ? P2 :
                      (t == 3) ? P3 : P4) + (size_t)hi * SLAB;

    float4 p[8];
    float4 cp = make_float4(0.f, 0.f, 0.f, 0.f);
    #pragma unroll
    for (int jj = 0; jj < 8; jj++) {
        int j = part * 8 + jj;
        p[jj] = __ldcs((const float4*)(P + j * 128 + c0));
        float kj = k_s[j];
        cp.x += kj * p[jj].x;
        cp.y += kj * p[jj].y;
        cp.z += kj * p[jj].z;
        cp.w += kj * p[jj].w;
    }
    red4[part][cq] = cp;
    __syncthreads();

    float4 contr = make_float4(0.f, 0.f, 0.f, 0.f);
    #pragma unroll
    for (int pp = 0; pp < 16; pp++) {
        float4 r = red4[pp][cq];
        contr.x += r.x; contr.y += r.y; contr.z += r.z; contr.w += r.w;
    }

    float al = g_AL[hi];
    float ba = g_BA[hi];
    float* op = out + OFF_SM + (size_t)t * SM_SZ + (size_t)hi * SLAB;

    if (t == 4) {
        // D_k[i,j,c] = u_i*delta_{jc} - ba_i*S[i,c]*k_j ; rec term shared
        float u = g_U[hi];
        float Ax = ba * contr.x + ba * S_s[c0 + 0];
        float Ay = ba * contr.y + ba * S_s[c0 + 1];
        float Az = ba * contr.z + ba * S_s[c0 + 2];
        float Aw = ba * contr.w + ba * S_s[c0 + 3];
        #pragma unroll
        for (int jj = 0; jj < 8; jj++) {
            int j = part * 8 + jj;
            float kj = k_s[j];
            float4 v;
            v.x = al * p[jj].x - Ax * kj;
            v.y = al * p[jj].y - Ay * kj;
            v.z = al * p[jj].z - Az * kj;
            v.w = al * p[jj].w - Aw * kj;
            if (j == c0 + 0) v.x += u;
            if (j == c0 + 1) v.y += u;
            if (j == c0 + 2) v.z += u;
            if (j == c0 + 3) v.w += u;
            __stcs((float4*)(op + j * 128 + c0), v);
        }
    } else {
        // direct terms live only in column c == i
        float cfK, cfS = 0.f;
        if (t == 0)       cfK = g_CW[hi];
        else if (t == 1) { cfK = -g_CZ2[hi]; cfS = g_ALP[hi]; }
        else if (t == 2)  cfK = g_CB[hi];
        else              cfK = g_CV[hi];
        float fx = (c0 + 0 == i) ? 1.f : 0.f;
        float fy = (c0 + 1 == i) ? 1.f : 0.f;
        float fz = (c0 + 2 == i) ? 1.f : 0.f;
        float fw = (c0 + 3 == i) ? 1.f : 0.f;
        float bcx = ba * contr.x, bcy = ba * contr.y;
        float bcz = ba * contr.z, bcw = ba * contr.w;
        #pragma unroll
        for (int jj = 0; jj < 8; jj++) {
            int j = part * 8 + jj;
            float kj = k_s[j];
            float dterm = cfK * kj + cfS * S_s[j];
            float4 v;
            v.x = al * p[jj].x - bcx * kj + fx * dterm;
            v.y = al * p[jj].y - bcy * kj + fy * dterm;
            v.z = al * p[jj].z - bcz * kj + fz * dterm;
            v.w = al * p[jj].w - bcw * kj + fw * dterm;
            __stcs((float4*)(op + j * 128 + c0), v);
        }
    }
}

extern "C" void kernel_launch(void* const* d_in, const int* in_sizes, int n_in,
                              void* d_out, int out_size) {
    const float* x    = (const float*)d_in[0];
    const float* S    = (const float*)d_in[1];
    const float* sm_w = (const float*)d_in[2];
    const float* sm_z = (const float*)d_in[3];
    const float* sm_b = (const float*)d_in[4];
    const float* sm_v = (const float*)d_in[5];
    const float* sm_k = (const float*)d_in[6];
    const float* W_w  = (const float*)d_in[7];
    const float* W_z  = (const float*)d_in[8];
    const float* W_b  = (const float*)d_in[9];
    const float* W_v  = (const float*)d_in[10];
    const float* W_k  = (const float*)d_in[11];
    const float* W_q  = (const float*)d_in[12];
    const float* W_o  = (const float*)d_in[13];
    const float* b_o  = (const float*)d_in[14];
    float* out = (float*)d_out;

    proj_kernel<<<144, 256>>>(x, W_k, W_q);
    row_kernel<<<1024, 128>>>(x, S, W_w, W_z, W_b, W_v, out);
    slab_kernel<<<10240, 256>>>(sm_w, sm_z, sm_b, sm_v, sm_k, S, W_o, b_o, out);
}